// round 1
// baseline (speedup 1.0000x reference)
#include <cuda_runtime.h>
#include <cuda_bf16.h>

#define N0 65536
#define N1 16384
#define N2 4096
#define N3 1024
#define N4 256
#define C  256

// output offsets (floats): pe4, pe3, pe2, pe1, pe0
#define OFF4 0
#define OFF3 (N4*C)                       // 65536
#define OFF2 (OFF3 + N3*C)                // 327680
#define OFF1 (OFF2 + N2*C)                // 1376256
#define OFF0 (OFF1 + N1*C)                // 5570560

// -------- scratch (device globals; no allocation allowed) --------
__device__ float g_f0[(size_t)N0 * C];    // 64 MB
__device__ float g_cls4[C];
__device__ float g_xyz1[N1 * 3];
__device__ float g_xyz2[N2 * 3];
__device__ float g_xyz3[N3 * 3];
__device__ float g_xyz4[N4 * 3];
__device__ int   g_k34[N3];
__device__ int   g_k23[N2];
__device__ int   g_k12[N1];

// -------- gather xyz rows --------
__global__ void gather_kernel(const float* __restrict__ xyz0,
                              const int* __restrict__ idx,
                              float* __restrict__ out, int M) {
    int i = blockIdx.x * blockDim.x + threadIdx.x;
    if (i < M) {
        int s = idx[i];
        out[i * 3 + 0] = xyz0[s * 3 + 0];
        out[i * 3 + 1] = xyz0[s * 3 + 1];
        out[i * 3 + 2] = xyz0[s * 3 + 2];
    }
}

// -------- f0 = xyz0 @ W_all + b_all --------
__global__ void f0_kernel(const float* __restrict__ xyz0,
                          const float* __restrict__ W,
                          const float* __restrict__ b,
                          float* __restrict__ f0) {
    int row = blockIdx.x;
    int t = threadIdx.x;
    float x = xyz0[row * 3 + 0];
    float y = xyz0[row * 3 + 1];
    float z = xyz0[row * 3 + 2];
    f0[(size_t)row * C + t] =
        fmaf(x, W[t], fmaf(y, W[C + t], fmaf(z, W[2 * C + t], b[t])));
}

// -------- cls4 = max over first 256 rows of f0 (per column) --------
__global__ void cls4_kernel(const float* __restrict__ f0, float* __restrict__ cls4) {
    int t = threadIdx.x;
    float m = -3.4e38f;
    for (int i = 0; i < N4; i++) m = fmaxf(m, f0[(size_t)i * C + t]);
    cls4[t] = m;
}

// -------- 1-NN: for each query row, argmin over refs of squared dist --------
// d = |r|^2 - 2 q.r  (|q|^2 dropped: monotone-equivalent). Strict < keeps first index.
__global__ void nn_kernel(const float* __restrict__ q, int Mq,
                          const float* __restrict__ ref, int Mr,
                          int* __restrict__ out) {
    const int CH = 1024;
    __shared__ float rx[CH], ry[CH], rz[CH], rn[CH];
    int tid = blockIdx.x * blockDim.x + threadIdx.x;
    float qx = q[tid * 3 + 0];
    float qy = q[tid * 3 + 1];
    float qz = q[tid * 3 + 2];
    float m2x = -2.0f * qx, m2y = -2.0f * qy, m2z = -2.0f * qz;
    float best = 3.4e38f;
    int bi = 0;
    for (int base = 0; base < Mr; base += CH) {
        int n = min(CH, Mr - base);
        for (int j = threadIdx.x; j < n; j += blockDim.x) {
            float x = ref[(base + j) * 3 + 0];
            float y = ref[(base + j) * 3 + 1];
            float z = ref[(base + j) * 3 + 2];
            rx[j] = x; ry[j] = y; rz[j] = z;
            rn[j] = x * x + y * y + z * z;
        }
        __syncthreads();
        #pragma unroll 4
        for (int j = 0; j < n; j++) {
            float d = fmaf(m2x, rx[j], fmaf(m2y, ry[j], fmaf(m2z, rz[j], rn[j])));
            if (d < best) { best = d; bi = base + j; }
        }
        __syncthreads();
    }
    out[tid] = bi;
}

// -------- fused level kernel --------
// A[row] = [ f_nei(row) (256) | f0[row] (256) ],  out[row] = A[row] @ P + pb
// f_nei(row) = (level4 ? cls4 : pe_prev[k[row]]) + delta @ W + b
// delta = level4 ? xyzq[row] : xyzq[row] - xyzr[k[row]]
// Block: 256 threads, TM=16 rows/block. Thread t owns output column t.
#define TM 16
__global__ void __launch_bounds__(256)
pe_kernel(const float* __restrict__ pe_prev,
          const int* __restrict__ knn,
          const float* __restrict__ xyzq,
          const float* __restrict__ xyzr,
          const float* __restrict__ f0,
          const float* __restrict__ W,
          const float* __restrict__ b,
          const float* __restrict__ P,
          const float* __restrict__ pb,
          float* __restrict__ out,
          int level4) {
    __shared__ __align__(16) float As[2 * C * TM];  // 32 KB, k-major: As[k*TM + r]
    __shared__ float dxs[TM][3];
    __shared__ int ks[TM];

    const int t = threadIdx.x;
    const int rowbase = blockIdx.x * TM;

    if (t < TM) {
        int row = rowbase + t;
        float qx = xyzq[row * 3 + 0];
        float qy = xyzq[row * 3 + 1];
        float qz = xyzq[row * 3 + 2];
        if (level4) {
            ks[t] = 0;
            dxs[t][0] = qx; dxs[t][1] = qy; dxs[t][2] = qz;
        } else {
            int kk = knn[row];
            ks[t] = kk;
            dxs[t][0] = qx - xyzr[kk * 3 + 0];
            dxs[t][1] = qy - xyzr[kk * 3 + 1];
            dxs[t][2] = qz - xyzr[kk * 3 + 2];
        }
    }
    __syncthreads();

    // Stage A tile, k-major. Thread t handles row r = t&15, k-group = t>>4.
    // STS address word = k*16 + r -> lane-id-linear within warp -> conflict-free.
    {
        const int r = t & (TM - 1);
        const int row = rowbase + r;
        const float dx = dxs[r][0], dy = dxs[r][1], dz = dxs[r][2];
        const int krow = ks[r];
        const float* prow = level4 ? pe_prev : (pe_prev + (size_t)krow * C);
        const float* frow = f0 + (size_t)row * C;
        #pragma unroll
        for (int it = 0; it < 16; it++) {
            int k = (t >> 4) + 16 * it;
            float nei = __ldg(prow + k);
            float v = nei + fmaf(dx, __ldg(W + k),
                          fmaf(dy, __ldg(W + C + k),
                          fmaf(dz, __ldg(W + 2 * C + k), __ldg(b + k))));
            As[k * TM + (t & (TM - 1))] = v;
            As[(C + k) * TM + (t & (TM - 1))] = __ldg(frow + k);
        }
    }
    __syncthreads();

    // GEMM: thread t computes column t for 16 rows, packed as 8 f32x2 accumulators.
    unsigned long long acc[TM / 2];
    #pragma unroll
    for (int j = 0; j < TM / 2; j++) acc[j] = 0ULL;

    const float* Pc = P + t;
    #pragma unroll 4
    for (int k = 0; k < 2 * C; k++) {
        float pv = __ldg(Pc + (size_t)k * C);
        unsigned long long pv2;
        asm("mov.b64 %0, {%1, %2};" : "=l"(pv2) : "f"(pv), "f"(pv));
        const unsigned long long* a2 =
            reinterpret_cast<const unsigned long long*>(&As[k * TM]);
        #pragma unroll
        for (int j = 0; j < TM / 2; j++) {
            asm("fma.rn.f32x2 %0, %1, %2, %0;"
                : "+l"(acc[j]) : "l"(a2[j]), "l"(pv2));
        }
    }

    float pbv = pb[t];
    #pragma unroll
    for (int j = 0; j < TM / 2; j++) {
        float lo, hi;
        asm("mov.b64 {%0, %1}, %2;" : "=f"(lo), "=f"(hi) : "l"(acc[j]));
        out[(size_t)(rowbase + 2 * j) * C + t]     = lo + pbv;
        out[(size_t)(rowbase + 2 * j + 1) * C + t] = hi + pbv;
    }
}

extern "C" void kernel_launch(void* const* d_in, const int* in_sizes, int n_in,
                              void* d_out, int out_size) {
    const float* xyz0 = (const float*)d_in[0];
    const int* idx0 = (const int*)d_in[1];
    const int* idx1 = (const int*)d_in[2];
    const int* idx2 = (const int*)d_in[3];
    const int* idx3 = (const int*)d_in[4];
    const int* idx4 = (const int*)d_in[5];
    const float* W_all = (const float*)d_in[6];
    const float* b_all = (const float*)d_in[7];
    const float* W4 = (const float*)d_in[8];
    const float* b4 = (const float*)d_in[9];
    const float* W3 = (const float*)d_in[10];
    const float* b3 = (const float*)d_in[11];
    const float* W2 = (const float*)d_in[12];
    const float* b2 = (const float*)d_in[13];
    const float* W1 = (const float*)d_in[14];
    const float* b1 = (const float*)d_in[15];
    const float* W0 = (const float*)d_in[16];
    const float* b0 = (const float*)d_in[17];
    const float* P4 = (const float*)d_in[18];
    const float* pb4 = (const float*)d_in[19];
    const float* P3 = (const float*)d_in[20];
    const float* pb3 = (const float*)d_in[21];
    const float* P2 = (const float*)d_in[22];
    const float* pb2 = (const float*)d_in[23];
    const float* P1 = (const float*)d_in[24];
    const float* pb1 = (const float*)d_in[25];
    const float* P0 = (const float*)d_in[26];
    const float* pb0 = (const float*)d_in[27];
    float* out = (float*)d_out;

    float *f0p, *cls4p, *x1, *x2, *x3, *x4;
    int *k34, *k23, *k12;
    cudaGetSymbolAddress((void**)&f0p, g_f0);
    cudaGetSymbolAddress((void**)&cls4p, g_cls4);
    cudaGetSymbolAddress((void**)&x1, g_xyz1);
    cudaGetSymbolAddress((void**)&x2, g_xyz2);
    cudaGetSymbolAddress((void**)&x3, g_xyz3);
    cudaGetSymbolAddress((void**)&x4, g_xyz4);
    cudaGetSymbolAddress((void**)&k34, g_k34);
    cudaGetSymbolAddress((void**)&k23, g_k23);
    cudaGetSymbolAddress((void**)&k12, g_k12);

    // gathers
    gather_kernel<<<(N1 + 255) / 256, 256>>>(xyz0, idx1, x1, N1);
    gather_kernel<<<(N2 + 255) / 256, 256>>>(xyz0, idx2, x2, N2);
    gather_kernel<<<(N3 + 255) / 256, 256>>>(xyz0, idx3, x3, N3);
    gather_kernel<<<(N4 + 255) / 256, 256>>>(xyz0, idx4, x4, N4);

    // f0 and cls4
    f0_kernel<<<N0, 256>>>(xyz0, W_all, b_all, f0p);
    cls4_kernel<<<1, 256>>>(f0p, cls4p);

    // nearest-neighbor maps (depend only on gathers)
    nn_kernel<<<N3 / 256, 256>>>(x3, N3, x4, N4, k34);
    nn_kernel<<<N2 / 256, 256>>>(x2, N2, x3, N3, k23);
    nn_kernel<<<N1 / 256, 256>>>(x1, N1, x2, N2, k12);

    // level chain (pe4 -> pe0), written directly to d_out
    pe_kernel<<<N4 / TM, 256>>>(cls4p, k34, x4, x4, f0p, W4, b4, P4, pb4, out + OFF4, 1);
    pe_kernel<<<N3 / TM, 256>>>(out + OFF4, k34, x3, x4, f0p, W3, b3, P3, pb3, out + OFF3, 0);
    pe_kernel<<<N2 / TM, 256>>>(out + OFF3, k23, x2, x3, f0p, W2, b2, P2, pb2, out + OFF2, 0);
    pe_kernel<<<N1 / TM, 256>>>(out + OFF2, k12, x1, x2, f0p, W1, b1, P1, pb1, out + OFF1, 0);
    pe_kernel<<<N0 / TM, 256>>>(out + OFF1, idx0, xyz0, x1, f0p, W0, b0, P0, pb0, out + OFF0, 0);
}